// round 3
// baseline (speedup 1.0000x reference)
#include <cuda_runtime.h>
#include <cstdint>

// Problem constants (fixed by the dataset):
//   x   [4096, 128]        fp32
//   src [4096, 32768]      fp32
//   tgt [4096, 32768]      fp32
//   f_w [128, 256]         fp32
//   f_b [128]              fp32
//   out [4096, 128]        fp32
#define NN 4096
#define EE 32768
#define DD 128
#define KSPLIT 8
#define KCHUNK (EE / KSPLIT)   // 4096

// Scratch (static __device__ — no runtime allocation)
__device__ float g_u[NN * DD];
__device__ float g_v[NN * DD];
__device__ float g_y[(size_t)EE * DD];
__device__ float g_part[(size_t)KSPLIT * NN * DD];

// ---- packed fp32x2 helpers (Blackwell FFMA2, only reachable via PTX) ----
__device__ __forceinline__ unsigned long long pack_dup(float a) {
    unsigned long long p;
    asm("mov.b64 %0, {%1, %1};" : "=l"(p) : "r"(__float_as_uint(a)));
    return p;
}
__device__ __forceinline__ void ffma2(unsigned long long& d,
                                      unsigned long long a,
                                      unsigned long long b) {
    asm("fma.rn.f32x2 %0, %1, %2, %0;" : "+l"(d) : "l"(a), "l"(b));
}
__device__ __forceinline__ float lo32(unsigned long long v) { return __uint_as_float((unsigned)v); }
__device__ __forceinline__ float hi32(unsigned long long v) { return __uint_as_float((unsigned)(v >> 32)); }

// ============================================================
// Kernel 1: node transform  u = x @ W1^T,  v = x @ W2^T
//   u[n,o] = sum_k x[n,k] * f_w[o, k]
//   v[n,o] = sum_k x[n,k] * f_w[o, 128+k]
// grid = 128 blocks (32 node-rows each), 256 threads:
//   threads 0..127 -> u column o=tid, threads 128..255 -> v column o=tid-128
// ============================================================
__global__ __launch_bounds__(256) void node_transform_kernel(
    const float* __restrict__ x, const float* __restrict__ fw)
{
    __shared__ __align__(16) float xs[32][DD];
    const int tid = threadIdx.x;
    const int n0 = blockIdx.x * 32;

    // load 32 x-rows (4096 floats = 1024 float4)
    #pragma unroll
    for (int l = 0; l < 4; ++l) {
        int idx = tid + l * 256;
        int r = idx >> 5;
        int c = (idx & 31) << 2;
        *(float4*)&xs[r][c] = *(const float4*)&x[(size_t)(n0 + r) * DD + c];
    }
    __syncthreads();

    const int half = tid >> 7;          // 0 -> u, 1 -> v
    const int o    = tid & 127;
    const float* fwrow = fw + (size_t)o * 256 + half * 128;

    float acc[32];
    #pragma unroll
    for (int n = 0; n < 32; ++n) acc[n] = 0.0f;

    #pragma unroll
    for (int kt = 0; kt < DD; kt += 32) {
        float fwreg[32];
        #pragma unroll
        for (int k = 0; k < 32; k += 4) {
            float4 f = *(const float4*)&fwrow[kt + k];
            fwreg[k] = f.x; fwreg[k + 1] = f.y; fwreg[k + 2] = f.z; fwreg[k + 3] = f.w;
        }
        #pragma unroll
        for (int n = 0; n < 32; ++n) {
            #pragma unroll
            for (int k = 0; k < 32; k += 4) {
                float4 xv = *(const float4*)&xs[n][kt + k];   // broadcast within warp
                acc[n] += xv.x * fwreg[k]     + xv.y * fwreg[k + 1]
                        + xv.z * fwreg[k + 2] + xv.w * fwreg[k + 3];
            }
        }
    }

    float* outp = half ? g_v : g_u;
    #pragma unroll
    for (int n = 0; n < 32; ++n)
        outp[(size_t)(n0 + n) * DD + o] = acc[n];
}

// ============================================================
// Kernel 2: fused gather GEMM + bias + relu
//   y[e,o] = relu( sum_n src[n,e]*u[n,o] + sum_n tgt[n,e]*v[n,o] + b[o] )
// M=32768 (e), N=128 (o), K = 4096 per phase, 2 phases.
// Tiles: 128x128, BK=16, 256 threads, 8x8 per thread (fp32x2 packed FMA).
// grid = 256 (e tiles)
// ============================================================
__global__ __launch_bounds__(256) void gather_kernel(
    const float* __restrict__ src, const float* __restrict__ tgt,
    const float* __restrict__ fb)
{
    __shared__ __align__(16) float As[16][128];   // [k][e]
    __shared__ __align__(16) float Bs[16][128];   // [k][o]

    const int tid = threadIdx.x;
    const int tx = tid & 15;        // o-direction
    const int ty = tid >> 4;        // e-direction
    const int e0 = blockIdx.x * 128;

    unsigned long long acc[8][4];
    #pragma unroll
    for (int i = 0; i < 8; ++i)
        #pragma unroll
        for (int j = 0; j < 4; ++j) acc[i][j] = 0ULL;

    #pragma unroll 1
    for (int phase = 0; phase < 2; ++phase) {
        const float* A = phase ? tgt : src;      // A[k,e] = mat[n=k, e]
        const float* B = phase ? g_v : g_u;      // B[k,o]

        #pragma unroll 1
        for (int k0 = 0; k0 < NN; k0 += 16) {
            #pragma unroll
            for (int l = 0; l < 2; ++l) {
                int idx = tid + l * 256;         // 0..511
                int r = idx >> 5;                // 0..15
                int c = (idx & 31) << 2;         // 0..124
                *(float4*)&As[r][c] = *(const float4*)&A[(size_t)(k0 + r) * EE + e0 + c];
                *(float4*)&Bs[r][c] = *(const float4*)&B[(size_t)(k0 + r) * DD + c];
            }
            __syncthreads();

            #pragma unroll
            for (int kk = 0; kk < 16; ++kk) {
                float4 a0 = *(const float4*)&As[kk][ty * 8];
                float4 a1 = *(const float4*)&As[kk][ty * 8 + 4];
                float4 b0 = *(const float4*)&Bs[kk][tx * 8];
                float4 b1 = *(const float4*)&Bs[kk][tx * 8 + 4];
                unsigned long long bb[4];
                { unsigned long long p;
                  asm("mov.b64 %0, {%1, %2};" : "=l"(p) : "r"(__float_as_uint(b0.x)), "r"(__float_as_uint(b0.y))); bb[0] = p;
                  asm("mov.b64 %0, {%1, %2};" : "=l"(p) : "r"(__float_as_uint(b0.z)), "r"(__float_as_uint(b0.w))); bb[1] = p;
                  asm("mov.b64 %0, {%1, %2};" : "=l"(p) : "r"(__float_as_uint(b1.x)), "r"(__float_as_uint(b1.y))); bb[2] = p;
                  asm("mov.b64 %0, {%1, %2};" : "=l"(p) : "r"(__float_as_uint(b1.z)), "r"(__float_as_uint(b1.w))); bb[3] = p;
                }
                float av[8] = {a0.x, a0.y, a0.z, a0.w, a1.x, a1.y, a1.z, a1.w};
                #pragma unroll
                for (int i = 0; i < 8; ++i) {
                    unsigned long long ad = pack_dup(av[i]);
                    ffma2(acc[i][0], ad, bb[0]);
                    ffma2(acc[i][1], ad, bb[1]);
                    ffma2(acc[i][2], ad, bb[2]);
                    ffma2(acc[i][3], ad, bb[3]);
                }
            }
            __syncthreads();
        }
    }

    // epilogue: + bias, relu, store y
    #pragma unroll
    for (int i = 0; i < 8; ++i) {
        int e = e0 + ty * 8 + i;
        #pragma unroll
        for (int j = 0; j < 4; ++j) {
            int o = tx * 8 + j * 2;
            float2 bo = *(const float2*)&fb[o];
            float lo = fmaxf(lo32(acc[i][j]) + bo.x, 0.0f);
            float hi = fmaxf(hi32(acc[i][j]) + bo.y, 0.0f);
            float2 st; st.x = lo; st.y = hi;
            *(float2*)&g_y[(size_t)e * DD + o] = st;
        }
    }
}

// ============================================================
// Kernel 3: scatter GEMM (split-K partials)
//   part[kc][n,o] = sum_{e in chunk kc} tgt[n,e] * y[e,o]
// M=4096 (n), N=128 (o), K=32768 split into 8 chunks of 4096.
// grid = (32, 8): x = n-tile, y = K chunk. Deterministic (no atomics).
// ============================================================
__global__ __launch_bounds__(256) void scatter_kernel(const float* __restrict__ tgt)
{
    __shared__ __align__(16) float As[128][20];   // [m=n][k], padded row (20 floats)
    __shared__ __align__(16) float Bs[16][128];   // [k][o]

    const int tid = threadIdx.x;
    const int tx = tid & 15;
    const int ty = tid >> 4;
    const int n0 = blockIdx.x * 128;
    const int kbase = blockIdx.y * KCHUNK;

    unsigned long long acc[8][4];
    #pragma unroll
    for (int i = 0; i < 8; ++i)
        #pragma unroll
        for (int j = 0; j < 4; ++j) acc[i][j] = 0ULL;

    #pragma unroll 1
    for (int k0 = kbase; k0 < kbase + KCHUNK; k0 += 16) {
        #pragma unroll
        for (int l = 0; l < 2; ++l) {
            int idx = tid + l * 256;          // 0..511
            // A tile: tgt rows are K-contiguous -> store m-major
            int m  = idx >> 2;                // 0..127
            int kq = (idx & 3) << 2;          // 0,4,8,12
            *(float4*)&As[m][kq] = *(const float4*)&tgt[(size_t)(n0 + m) * EE + k0 + kq];
            // B tile: y[k, o]
            int r = idx >> 5;
            int c = (idx & 31) << 2;
            *(float4*)&Bs[r][c] = *(const float4*)&g_y[(size_t)(k0 + r) * DD + c];
        }
        __syncthreads();

        #pragma unroll
        for (int kk = 0; kk < 16; ++kk) {
            float av[8];
            #pragma unroll
            for (int i = 0; i < 8; ++i) av[i] = As[ty * 8 + i][kk];  // warp-broadcast
            float4 b0 = *(const float4*)&Bs[kk][tx * 8];
            float4 b1 = *(const float4*)&Bs[kk][tx * 8 + 4];
            unsigned long long bb[4];
            { unsigned long long p;
              asm("mov.b64 %0, {%1, %2};" : "=l"(p) : "r"(__float_as_uint(b0.x)), "r"(__float_as_uint(b0.y))); bb[0] = p;
              asm("mov.b64 %0, {%1, %2};" : "=l"(p) : "r"(__float_as_uint(b0.z)), "r"(__float_as_uint(b0.w))); bb[1] = p;
              asm("mov.b64 %0, {%1, %2};" : "=l"(p) : "r"(__float_as_uint(b1.x)), "r"(__float_as_uint(b1.y))); bb[2] = p;
              asm("mov.b64 %0, {%1, %2};" : "=l"(p) : "r"(__float_as_uint(b1.z)), "r"(__float_as_uint(b1.w))); bb[3] = p;
            }
            #pragma unroll
            for (int i = 0; i < 8; ++i) {
                unsigned long long ad = pack_dup(av[i]);
                ffma2(acc[i][0], ad, bb[0]);
                ffma2(acc[i][1], ad, bb[1]);
                ffma2(acc[i][2], ad, bb[2]);
                ffma2(acc[i][3], ad, bb[3]);
            }
        }
        __syncthreads();
    }

    float* part = &g_part[(size_t)blockIdx.y * NN * DD];
    #pragma unroll
    for (int i = 0; i < 8; ++i) {
        int n = n0 + ty * 8 + i;
        #pragma unroll
        for (int j = 0; j < 4; ++j) {
            int o = tx * 8 + j * 2;
            float2 st; st.x = lo32(acc[i][j]); st.y = hi32(acc[i][j]);
            *(float2*)&part[(size_t)n * DD + o] = st;
        }
    }
}

// ============================================================
// Kernel 4: reduce split-K partials into d_out (deterministic)
// ============================================================
__global__ __launch_bounds__(256) void reduce_kernel(float* __restrict__ out)
{
    int i = blockIdx.x * blockDim.x + threadIdx.x;   // 0 .. 524287
    float s = 0.0f;
    #pragma unroll
    for (int p = 0; p < KSPLIT; ++p)
        s += g_part[(size_t)p * NN * DD + i];
    out[i] = s;
}

// ============================================================
extern "C" void kernel_launch(void* const* d_in, const int* in_sizes, int n_in,
                              void* d_out, int out_size)
{
    const float* x   = (const float*)d_in[0];
    const float* src = (const float*)d_in[1];
    const float* tgt = (const float*)d_in[2];
    const float* fw  = (const float*)d_in[3];
    const float* fb  = (const float*)d_in[4];
    float* out = (float*)d_out;

    node_transform_kernel<<<NN / 32, 256>>>(x, fw);
    gather_kernel<<<EE / 128, 256>>>(src, tgt, fb);
    scatter_kernel<<<dim3(NN / 128, KSPLIT), 256>>>(tgt);
    reduce_kernel<<<(NN * DD) / 256, 256>>>(out);
}

// round 6
// speedup vs baseline: 3.8966x; 3.8966x over previous
#include <cuda_runtime.h>
#include <cstdint>

#define NN 4096
#define EE 32768
#define DD 128
#define KSPLIT 8

// ---------------- scratch (static __device__, no runtime alloc) ----------------
// g_B2 : [8192][128]  rows 0..4095 = u = x@W1^T, rows 4096..8191 = v (tf32-rounded fp32)
// g_y  : [32768][128] relu(...) tf32-rounded fp32
__device__ __align__(16) float g_B2[(2 * NN) * DD];
__device__ __align__(16) float g_y [(size_t)EE * DD];
__device__ __align__(16) float g_part[(size_t)KSPLIT * NN * DD];

// ---------------- helpers ----------------
__device__ __forceinline__ uint32_t smaddr(const void* p) {
    return (uint32_t)__cvta_generic_to_shared(p);
}
__device__ __forceinline__ void cpasync16(uint32_t s, const void* g) {
    asm volatile("cp.async.cg.shared.global [%0], [%1], 16;" :: "r"(s), "l"(g) : "memory");
}
#define CP_COMMIT() asm volatile("cp.async.commit_group;" ::: "memory")
#define CP_WAIT1()  asm volatile("cp.async.wait_group 1;" ::: "memory")

__device__ __forceinline__ uint32_t cvt_tf32(float f) {
    uint32_t t;
    asm("cvt.rna.tf32.f32 %0, %1;" : "=r"(t) : "f"(f));
    return t;
}
__device__ __forceinline__ void mma_tf32(float* c, const uint32_t* a, const uint32_t* b) {
    asm volatile(
        "mma.sync.aligned.m16n8k8.row.col.f32.tf32.tf32.f32 "
        "{%0,%1,%2,%3}, {%4,%5,%6,%7}, {%8,%9}, {%0,%1,%2,%3};"
        : "+f"(c[0]), "+f"(c[1]), "+f"(c[2]), "+f"(c[3])
        : "r"(a[0]), "r"(a[1]), "r"(a[2]), "r"(a[3]), "r"(b[0]), "r"(b[1]));
}

// ============================================================
// Kernel 1: node transform u=x@W1^T, v=x@W2^T -> g_B2 (tf32-rounded)
// ============================================================
__global__ __launch_bounds__(256) void node_transform_kernel(
    const float* __restrict__ x, const float* __restrict__ fw)
{
    __shared__ __align__(16) float xs[32][DD];
    const int tid = threadIdx.x;
    const int n0 = blockIdx.x * 32;

    #pragma unroll
    for (int l = 0; l < 4; ++l) {
        int idx = tid + l * 256;
        int r = idx >> 5, c = (idx & 31) << 2;
        *(float4*)&xs[r][c] = *(const float4*)&x[(size_t)(n0 + r) * DD + c];
    }
    __syncthreads();

    const int half = tid >> 7;
    const int o    = tid & 127;
    const float* fwrow = fw + (size_t)o * 256 + half * 128;

    float acc[32];
    #pragma unroll
    for (int n = 0; n < 32; ++n) acc[n] = 0.0f;

    #pragma unroll
    for (int kt = 0; kt < DD; kt += 32) {
        float fwreg[32];
        #pragma unroll
        for (int k = 0; k < 32; k += 4) {
            float4 f = *(const float4*)&fwrow[kt + k];
            fwreg[k] = f.x; fwreg[k+1] = f.y; fwreg[k+2] = f.z; fwreg[k+3] = f.w;
        }
        #pragma unroll
        for (int n = 0; n < 32; ++n) {
            #pragma unroll
            for (int k = 0; k < 32; k += 4) {
                float4 xv = *(const float4*)&xs[n][kt + k];
                acc[n] += xv.x*fwreg[k] + xv.y*fwreg[k+1] + xv.z*fwreg[k+2] + xv.w*fwreg[k+3];
            }
        }
    }

    #pragma unroll
    for (int n = 0; n < 32; ++n)
        g_B2[(size_t)(half * NN + n0 + n) * DD + o] = __uint_as_float(cvt_tf32(acc[n]));
}

// ============================================================
// Kernel 2: gather GEMM (mma.sync tf32) + bias + relu -> g_y
//   y[e,o] = relu( sum_k A[k,e]*B[k,o] + b[o] ),
//   A = [src; tgt] (k = 0..8191 rows), B = g_B2.
// CTA tile 256(e) x 128(o), BK=32, 3-stage cp.async, 8 warps (4x2), warp 64x64.
// grid = 128.
// ============================================================
#define G_ASTRIDE 264               // 256 + 8 pad (1056B: frag rows land on distinct banks)
#define G_BSTRIDE 136               // 128 + 8 pad
#define G_ASZ (32 * G_ASTRIDE)      // floats per stage
#define G_BSZ (32 * G_BSTRIDE)

__global__ __launch_bounds__(256, 1) void gather_kernel(
    const float* __restrict__ src, const float* __restrict__ tgt,
    const float* __restrict__ fb)
{
    extern __shared__ float sm[];
    float* As = sm;                  // [3][32][264]  (k-major)
    float* Bs = sm + 3 * G_ASZ;      // [3][32][136]

    const int tid  = threadIdx.x;
    const int lane = tid & 31;
    const int wid  = tid >> 5;
    const int wm   = wid >> 1;       // 0..3  (e)
    const int wn   = wid & 1;        // 0..1  (o)
    const int e0   = blockIdx.x * 256;

    float acc[4][8][4];
    #pragma unroll
    for (int mt = 0; mt < 4; ++mt)
        #pragma unroll
        for (int nt = 0; nt < 8; ++nt)
            #pragma unroll
            for (int q = 0; q < 4; ++q) acc[mt][nt][q] = 0.0f;

    auto load_stage = [&](int st, int kt) {
        float* Ad = As + st * G_ASZ;
        float* Bd = Bs + st * G_BSZ;
        #pragma unroll
        for (int l = 0; l < 8; ++l) {
            int idx = tid + l * 256;
            int r = idx >> 6;                 // 0..31
            int c = (idx & 63) << 2;          // 0..252
            int kk = kt * 32 + r;
            const float* gp = (kk < NN) ? (src + (size_t)kk * EE + e0 + c)
                                        : (tgt + (size_t)(kk - NN) * EE + e0 + c);
            cpasync16(smaddr(Ad + r * G_ASTRIDE + c), gp);
        }
        #pragma unroll
        for (int l = 0; l < 4; ++l) {
            int idx = tid + l * 256;
            int r = idx >> 5;                 // 0..31
            int c = (idx & 31) << 2;          // 0..124
            cpasync16(smaddr(Bd + r * G_BSTRIDE + c),
                      g_B2 + (size_t)(kt * 32 + r) * DD + c);
        }
    };

    const int KT = (2 * NN) / 32;    // 256
    load_stage(0, 0); CP_COMMIT();
    load_stage(1, 1); CP_COMMIT();

    #pragma unroll 1
    for (int kt = 0; kt < KT; ++kt) {
        CP_WAIT1();
        __syncthreads();
        if (kt + 2 < KT) load_stage((kt + 2) % 3, kt + 2);
        CP_COMMIT();

        const float* Ac = As + (kt % 3) * G_ASZ;
        const float* Bc = Bs + (kt % 3) * G_BSZ;
        #pragma unroll
        for (int kk = 0; kk < 4; ++kk) {
            const int k = kk * 8 + (lane & 3);
            uint32_t af[4][4];
            #pragma unroll
            for (int mt = 0; mt < 4; ++mt) {
                int e = wm * 64 + mt * 16 + (lane >> 2);
                af[mt][0] = cvt_tf32(Ac[k * G_ASTRIDE + e]);
                af[mt][1] = cvt_tf32(Ac[k * G_ASTRIDE + e + 8]);
                af[mt][2] = cvt_tf32(Ac[(k + 4) * G_ASTRIDE + e]);
                af[mt][3] = cvt_tf32(Ac[(k + 4) * G_ASTRIDE + e + 8]);
            }
            uint32_t bf[8][2];
            #pragma unroll
            for (int nt = 0; nt < 8; ++nt) {
                int o = wn * 64 + nt * 8 + (lane >> 2);
                bf[nt][0] = __float_as_uint(Bc[k * G_BSTRIDE + o]);
                bf[nt][1] = __float_as_uint(Bc[(k + 4) * G_BSTRIDE + o]);
            }
            #pragma unroll
            for (int mt = 0; mt < 4; ++mt)
                #pragma unroll
                for (int nt = 0; nt < 8; ++nt)
                    mma_tf32(acc[mt][nt], af[mt], bf[nt]);
        }
        __syncthreads();
    }

    // epilogue: + bias, relu, tf32-round, store y[e][o]
    #pragma unroll
    for (int mt = 0; mt < 4; ++mt) {
        int e = e0 + wm * 64 + mt * 16 + (lane >> 2);
        #pragma unroll
        for (int nt = 0; nt < 8; ++nt) {
            int o = wn * 64 + nt * 8 + ((lane & 3) << 1);
            float b0 = __ldg(fb + o), b1 = __ldg(fb + o + 1);
            float2 r0, r1;
            r0.x = __uint_as_float(cvt_tf32(fmaxf(acc[mt][nt][0] + b0, 0.0f)));
            r0.y = __uint_as_float(cvt_tf32(fmaxf(acc[mt][nt][1] + b1, 0.0f)));
            r1.x = __uint_as_float(cvt_tf32(fmaxf(acc[mt][nt][2] + b0, 0.0f)));
            r1.y = __uint_as_float(cvt_tf32(fmaxf(acc[mt][nt][3] + b1, 0.0f)));
            *(float2*)&g_y[(size_t)e * DD + o]       = r0;
            *(float2*)&g_y[(size_t)(e + 8) * DD + o] = r1;
        }
    }
}

// ============================================================
// Kernel 3: scatter GEMM (mma.sync tf32, split-K partials)
//   part[kc][n,o] = sum_{e in chunk} tgt[n,e] * y[e,o]
// CTA tile 256(n) x 128(o), K=4096/CTA, BK=32, 3-stage. grid=(16, 8).
// ============================================================
#define S_ASTRIDE 36                // 32 + 4 pad (144B: frag rows on distinct banks)
#define S_ASZ (256 * S_ASTRIDE)
#define S_BSZ (32 * G_BSTRIDE)

__global__ __launch_bounds__(256, 1) void scatter_kernel(const float* __restrict__ tgt)
{
    extern __shared__ float sm[];
    float* As = sm;                  // [3][256][36]  (m-major)
    float* Bs = sm + 3 * S_ASZ;      // [3][32][136]

    const int tid  = threadIdx.x;
    const int lane = tid & 31;
    const int wid  = tid >> 5;
    const int wm   = wid >> 1;
    const int wn   = wid & 1;
    const int n0   = blockIdx.x * 256;
    const int kb   = blockIdx.y * (EE / KSPLIT);

    float acc[4][8][4];
    #pragma unroll
    for (int mt = 0; mt < 4; ++mt)
        #pragma unroll
        for (int nt = 0; nt < 8; ++nt)
            #pragma unroll
            for (int q = 0; q < 4; ++q) acc[mt][nt][q] = 0.0f;

    auto load_stage = [&](int st, int kt) {
        float* Ad = As + st * S_ASZ;
        float* Bd = Bs + st * S_BSZ;
        #pragma unroll
        for (int l = 0; l < 8; ++l) {
            int idx = tid + l * 256;
            int m  = idx >> 3;                // 0..255
            int kq = (idx & 7) << 2;          // 0..28
            cpasync16(smaddr(Ad + m * S_ASTRIDE + kq),
                      tgt + (size_t)(n0 + m) * EE + kb + kt * 32 + kq);
        }
        #pragma unroll
        for (int l = 0; l < 4; ++l) {
            int idx = tid + l * 256;
            int r = idx >> 5;
            int c = (idx & 31) << 2;
            cpasync16(smaddr(Bd + r * G_BSTRIDE + c),
                      g_y + (size_t)(kb + kt * 32 + r) * DD + c);
        }
    };

    const int KT = (EE / KSPLIT) / 32;   // 128
    load_stage(0, 0); CP_COMMIT();
    load_stage(1, 1); CP_COMMIT();

    #pragma unroll 1
    for (int kt = 0; kt < KT; ++kt) {
        CP_WAIT1();
        __syncthreads();
        if (kt + 2 < KT) load_stage((kt + 2) % 3, kt + 2);
        CP_COMMIT();

        const float* Ac = As + (kt % 3) * S_ASZ;
        const float* Bc = Bs + (kt % 3) * S_BSZ;
        #pragma unroll
        for (int kk = 0; kk < 4; ++kk) {
            const int k = kk * 8 + (lane & 3);
            uint32_t af[4][4];
            #pragma unroll
            for (int mt = 0; mt < 4; ++mt) {
                int m = wm * 64 + mt * 16 + (lane >> 2);
                af[mt][0] = cvt_tf32(Ac[m * S_ASTRIDE + k]);
                af[mt][1] = cvt_tf32(Ac[(m + 8) * S_ASTRIDE + k]);
                af[mt][2] = cvt_tf32(Ac[m * S_ASTRIDE + k + 4]);
                af[mt][3] = cvt_tf32(Ac[(m + 8) * S_ASTRIDE + k + 4]);
            }
            uint32_t bf[8][2];
            #pragma unroll
            for (int nt = 0; nt < 8; ++nt) {
                int o = wn * 64 + nt * 8 + (lane >> 2);
                bf[nt][0] = __float_as_uint(Bc[k * G_BSTRIDE + o]);
                bf[nt][1] = __float_as_uint(Bc[(k + 4) * G_BSTRIDE + o]);
            }
            #pragma unroll
            for (int mt = 0; mt < 4; ++mt)
                #pragma unroll
                for (int nt = 0; nt < 8; ++nt)
                    mma_tf32(acc[mt][nt], af[mt], bf[nt]);
        }
        __syncthreads();
    }

    float* part = g_part + (size_t)blockIdx.y * NN * DD;
    #pragma unroll
    for (int mt = 0; mt < 4; ++mt) {
        int n = n0 + wm * 64 + mt * 16 + (lane >> 2);
        #pragma unroll
        for (int nt = 0; nt < 8; ++nt) {
            int o = wn * 64 + nt * 8 + ((lane & 3) << 1);
            float2 r0, r1;
            r0.x = acc[mt][nt][0]; r0.y = acc[mt][nt][1];
            r1.x = acc[mt][nt][2]; r1.y = acc[mt][nt][3];
            *(float2*)&part[(size_t)n * DD + o]       = r0;
            *(float2*)&part[(size_t)(n + 8) * DD + o] = r1;
        }
    }
}

// ============================================================
// Kernel 4: deterministic split-K reduce (float4)
// ============================================================
__global__ __launch_bounds__(256) void reduce_kernel(float* __restrict__ out)
{
    size_t i = ((size_t)blockIdx.x * 256 + threadIdx.x) * 4;
    float4 s = *(const float4*)&g_part[i];
    #pragma unroll
    for (int p = 1; p < KSPLIT; ++p) {
        float4 v = *(const float4*)&g_part[(size_t)p * NN * DD + i];
        s.x += v.x; s.y += v.y; s.z += v.z; s.w += v.w;
    }
    *(float4*)&out[i] = s;
}

// ============================================================
extern "C" void kernel_launch(void* const* d_in, const int* in_sizes, int n_in,
                              void* d_out, int out_size)
{
    const float* x   = (const float*)d_in[0];
    const float* src = (const float*)d_in[1];
    const float* tgt = (const float*)d_in[2];
    const float* fw  = (const float*)d_in[3];
    const float* fb  = (const float*)d_in[4];
    float* out = (float*)d_out;

    const int g_smem = 3 * (G_ASZ + G_BSZ) * sizeof(float);   // 153600
    const int s_smem = 3 * (S_ASZ + S_BSZ) * sizeof(float);   // 162816
    cudaFuncSetAttribute(gather_kernel,  cudaFuncAttributeMaxDynamicSharedMemorySize, g_smem);
    cudaFuncSetAttribute(scatter_kernel, cudaFuncAttributeMaxDynamicSharedMemorySize, s_smem);

    node_transform_kernel<<<NN / 32, 256>>>(x, fw);
    gather_kernel<<<EE / 256, 256, g_smem>>>(src, tgt, fb);
    scatter_kernel<<<dim3(NN / 256, KSPLIT), 256, s_smem>>>(tgt);
    reduce_kernel<<<(NN * DD) / 1024, 256>>>(out);
}

// round 8
// speedup vs baseline: 3.9450x; 1.0124x over previous
#include <cuda_runtime.h>
#include <cstdint>

#define NN 4096
#define EE 32768
#define DD 128
#define KSPLIT 8

// ---------------- scratch (static __device__, no runtime alloc) ----------------
// g_B2 : [8192][128]  rows 0..4095 = u = x@W1^T, rows 4096..8191 = v (tf32-rounded fp32)
// g_y  : [32768][128] relu(...) tf32-rounded fp32
__device__ __align__(16) float g_B2[(2 * NN) * DD];
__device__ __align__(16) float g_y [(size_t)EE * DD];
__device__ __align__(16) float g_part[(size_t)KSPLIT * NN * DD];

// ---------------- helpers ----------------
__device__ __forceinline__ uint32_t smaddr(const void* p) {
    return (uint32_t)__cvta_generic_to_shared(p);
}
__device__ __forceinline__ void cpasync16(uint32_t s, const void* g) {
    asm volatile("cp.async.cg.shared.global [%0], [%1], 16;" :: "r"(s), "l"(g) : "memory");
}
#define CP_COMMIT() asm volatile("cp.async.commit_group;" ::: "memory")
#define CP_WAIT2()  asm volatile("cp.async.wait_group 2;" ::: "memory")

__device__ __forceinline__ uint32_t cvt_tf32(float f) {
    uint32_t t;
    asm("cvt.rna.tf32.f32 %0, %1;" : "=r"(t) : "f"(f));
    return t;
}
__device__ __forceinline__ void mma_tf32(float* c, const uint32_t* a, const uint32_t* b) {
    asm volatile(
        "mma.sync.aligned.m16n8k8.row.col.f32.tf32.tf32.f32 "
        "{%0,%1,%2,%3}, {%4,%5,%6,%7}, {%8,%9}, {%0,%1,%2,%3};"
        : "+f"(c[0]), "+f"(c[1]), "+f"(c[2]), "+f"(c[3])
        : "r"(a[0]), "r"(a[1]), "r"(a[2]), "r"(a[3]), "r"(b[0]), "r"(b[1]));
}

// ============================================================
// Kernel 1: node transform u=x@W1^T, v=x@W2^T -> g_B2 (tf32-rounded)
// ============================================================
__global__ __launch_bounds__(256) void node_transform_kernel(
    const float* __restrict__ x, const float* __restrict__ fw)
{
    __shared__ __align__(16) float xs[32][DD];
    const int tid = threadIdx.x;
    const int n0 = blockIdx.x * 32;

    #pragma unroll
    for (int l = 0; l < 4; ++l) {
        int idx = tid + l * 256;
        int r = idx >> 5, c = (idx & 31) << 2;
        *(float4*)&xs[r][c] = *(const float4*)&x[(size_t)(n0 + r) * DD + c];
    }
    __syncthreads();

    const int half = tid >> 7;
    const int o    = tid & 127;
    const float* fwrow = fw + (size_t)o * 256 + half * 128;

    float acc[32];
    #pragma unroll
    for (int n = 0; n < 32; ++n) acc[n] = 0.0f;

    #pragma unroll
    for (int kt = 0; kt < DD; kt += 32) {
        float fwreg[32];
        #pragma unroll
        for (int k = 0; k < 32; k += 4) {
            float4 f = *(const float4*)&fwrow[kt + k];
            fwreg[k] = f.x; fwreg[k+1] = f.y; fwreg[k+2] = f.z; fwreg[k+3] = f.w;
        }
        #pragma unroll
        for (int n = 0; n < 32; ++n) {
            #pragma unroll
            for (int k = 0; k < 32; k += 4) {
                float4 xv = *(const float4*)&xs[n][kt + k];
                acc[n] += xv.x*fwreg[k] + xv.y*fwreg[k+1] + xv.z*fwreg[k+2] + xv.w*fwreg[k+3];
            }
        }
    }

    #pragma unroll
    for (int n = 0; n < 32; ++n)
        g_B2[(size_t)(half * NN + n0 + n) * DD + o] = __uint_as_float(cvt_tf32(acc[n]));
}

// ============================================================
// Kernel 2: gather GEMM (mma.sync tf32) + bias + relu -> g_y
//   y[e,o] = relu( sum_k A[k,e]*B[k,o] + b[o] ),  A = [src; tgt], B = g_B2.
// CTA tile 256(e) x 128(o), BK=32, 4-stage cp.async (prefetch depth 3, one
// barrier per k-tile), 8 warps (4x2), warp 64x64. grid = 128.
// ============================================================
#define G_ASTRIDE 264               // 256 + 8 pad
#define G_BSTRIDE 136               // 128 + 8 pad
#define G_ASZ (32 * G_ASTRIDE)      // floats per stage
#define G_BSZ (32 * G_BSTRIDE)
#define G_STG (G_ASZ + G_BSZ)       // 12800 floats / stage

__global__ __launch_bounds__(256, 1) void gather_kernel(
    const float* __restrict__ src, const float* __restrict__ tgt,
    const float* __restrict__ fb)
{
    extern __shared__ float sm[];    // [4][G_STG]:  A then B per stage

    const int tid  = threadIdx.x;
    const int lane = tid & 31;
    const int wid  = tid >> 5;
    const int wm   = wid >> 1;       // 0..3  (e)
    const int wn   = wid & 1;        // 0..1  (o)
    const int e0   = blockIdx.x * 256;

    float acc[4][8][4];
    #pragma unroll
    for (int mt = 0; mt < 4; ++mt)
        #pragma unroll
        for (int nt = 0; nt < 8; ++nt)
            #pragma unroll
            for (int q = 0; q < 4; ++q) acc[mt][nt][q] = 0.0f;

    auto load_stage = [&](int st, int kt) {
        float* Ad = sm + st * G_STG;
        float* Bd = Ad + G_ASZ;
        #pragma unroll
        for (int l = 0; l < 8; ++l) {
            int idx = tid + l * 256;
            int r = idx >> 6;                 // 0..31
            int c = (idx & 63) << 2;          // 0..252
            int kk = kt * 32 + r;
            const float* gp = (kk < NN) ? (src + (size_t)kk * EE + e0 + c)
                                        : (tgt + (size_t)(kk - NN) * EE + e0 + c);
            cpasync16(smaddr(Ad + r * G_ASTRIDE + c), gp);
        }
        #pragma unroll
        for (int l = 0; l < 4; ++l) {
            int idx = tid + l * 256;
            int r = idx >> 5;                 // 0..31
            int c = (idx & 31) << 2;          // 0..124
            cpasync16(smaddr(Bd + r * G_BSTRIDE + c),
                      g_B2 + (size_t)(kt * 32 + r) * DD + c);
        }
    };

    const int KT = (2 * NN) / 32;    // 256
    load_stage(0, 0); CP_COMMIT();
    load_stage(1, 1); CP_COMMIT();
    load_stage(2, 2); CP_COMMIT();

    #pragma unroll 1
    for (int kt = 0; kt < KT; ++kt) {
        CP_WAIT2();                  // stage kt landed (<=2 groups in flight)
        __syncthreads();             // visibility + (kt+3)&3 buffer free
        if (kt + 3 < KT) load_stage((kt + 3) & 3, kt + 3);
        CP_COMMIT();                 // commit every iter (may be empty) for group accounting

        const float* Ac = sm + (kt & 3) * G_STG;
        const float* Bc = Ac + G_ASZ;
        #pragma unroll
        for (int kk = 0; kk < 4; ++kk) {
            const int k = kk * 8 + (lane & 3);
            uint32_t af[4][4];
            #pragma unroll
            for (int mt = 0; mt < 4; ++mt) {
                int e = wm * 64 + mt * 16 + (lane >> 2);
                af[mt][0] = cvt_tf32(Ac[k * G_ASTRIDE + e]);
                af[mt][1] = cvt_tf32(Ac[k * G_ASTRIDE + e + 8]);
                af[mt][2] = cvt_tf32(Ac[(k + 4) * G_ASTRIDE + e]);
                af[mt][3] = cvt_tf32(Ac[(k + 4) * G_ASTRIDE + e + 8]);
            }
            uint32_t bf[8][2];
            #pragma unroll
            for (int nt = 0; nt < 8; ++nt) {
                int o = wn * 64 + nt * 8 + (lane >> 2);
                bf[nt][0] = __float_as_uint(Bc[k * G_BSTRIDE + o]);
                bf[nt][1] = __float_as_uint(Bc[(k + 4) * G_BSTRIDE + o]);
            }
            #pragma unroll
            for (int mt = 0; mt < 4; ++mt)
                #pragma unroll
                for (int nt = 0; nt < 8; ++nt)
                    mma_tf32(acc[mt][nt], af[mt], bf[nt]);
        }
        // no trailing barrier: next iteration's barrier protects buffer reuse
    }

    // epilogue: + bias, relu, tf32-round, store y[e][o]
    #pragma unroll
    for (int mt = 0; mt < 4; ++mt) {
        int e = e0 + wm * 64 + mt * 16 + (lane >> 2);
        #pragma unroll
        for (int nt = 0; nt < 8; ++nt) {
            int o = wn * 64 + nt * 8 + ((lane & 3) << 1);
            float b0 = __ldg(fb + o), b1 = __ldg(fb + o + 1);
            float2 r0, r1;
            r0.x = __uint_as_float(cvt_tf32(fmaxf(acc[mt][nt][0] + b0, 0.0f)));
            r0.y = __uint_as_float(cvt_tf32(fmaxf(acc[mt][nt][1] + b1, 0.0f)));
            r1.x = __uint_as_float(cvt_tf32(fmaxf(acc[mt][nt][2] + b0, 0.0f)));
            r1.y = __uint_as_float(cvt_tf32(fmaxf(acc[mt][nt][3] + b1, 0.0f)));
            *(float2*)&g_y[(size_t)e * DD + o]       = r0;
            *(float2*)&g_y[(size_t)(e + 8) * DD + o] = r1;
        }
    }
}

// ============================================================
// Kernel 3: scatter GEMM (mma.sync tf32, split-K partials)
//   part[kc][n,o] = sum_{e in chunk} tgt[n,e] * y[e,o]
// CTA tile 256(n) x 128(o), K=4096/CTA, BK=32, 4-stage, one barrier/kt.
// grid=(16, 8).
// ============================================================
#define S_ASTRIDE 36                // 32 + 4 pad
#define S_ASZ (256 * S_ASTRIDE)
#define S_BSZ (32 * G_BSTRIDE)
#define S_STG (S_ASZ + S_BSZ)       // 13568 floats / stage

__global__ __launch_bounds__(256, 1) void scatter_kernel(const float* __restrict__ tgt)
{
    extern __shared__ float sm[];    // [4][S_STG]

    const int tid  = threadIdx.x;
    const int lane = tid & 31;
    const int wid  = tid >> 5;
    const int wm   = wid >> 1;
    const int wn   = wid & 1;
    const int n0   = blockIdx.x * 256;
    const int kb   = blockIdx.y * (EE / KSPLIT);

    float acc[4][8][4];
    #pragma unroll
    for (int mt = 0; mt < 4; ++mt)
        #pragma unroll
        for (int nt = 0; nt < 8; ++nt)
            #pragma unroll
            for (int q = 0; q < 4; ++q) acc[mt][nt][q] = 0.0f;

    auto load_stage = [&](int st, int kt) {
        float* Ad = sm + st * S_STG;
        float* Bd = Ad + S_ASZ;
        #pragma unroll
        for (int l = 0; l < 8; ++l) {
            int idx = tid + l * 256;
            int m  = idx >> 3;                // 0..255
            int kq = (idx & 7) << 2;          // 0..28
            cpasync16(smaddr(Ad + m * S_ASTRIDE + kq),
                      tgt + (size_t)(n0 + m) * EE + kb + kt * 32 + kq);
        }
        #pragma unroll
        for (int l = 0; l < 4; ++l) {
            int idx = tid + l * 256;
            int r = idx >> 5;
            int c = (idx & 31) << 2;
            cpasync16(smaddr(Bd + r * G_BSTRIDE + c),
                      g_y + (size_t)(kb + kt * 32 + r) * DD + c);
        }
    };

    const int KT = (EE / KSPLIT) / 32;   // 128
    load_stage(0, 0); CP_COMMIT();
    load_stage(1, 1); CP_COMMIT();
    load_stage(2, 2); CP_COMMIT();

    #pragma unroll 1
    for (int kt = 0; kt < KT; ++kt) {
        CP_WAIT2();
        __syncthreads();
        if (kt + 3 < KT) load_stage((kt + 3) & 3, kt + 3);
        CP_COMMIT();

        const float* Ac = sm + (kt & 3) * S_STG;
        const float* Bc = Ac + S_ASZ;
        #pragma unroll
        for (int kk = 0; kk < 4; ++kk) {
            const int k = kk * 8 + (lane & 3);
            uint32_t af[4][4];
            #pragma unroll
            for (int mt = 0; mt < 4; ++mt) {
                int m = wm * 64 + mt * 16 + (lane >> 2);
                af[mt][0] = cvt_tf32(Ac[m * S_ASTRIDE + k]);
                af[mt][1] = cvt_tf32(Ac[(m + 8) * S_ASTRIDE + k]);
                af[mt][2] = cvt_tf32(Ac[m * S_ASTRIDE + k + 4]);
                af[mt][3] = cvt_tf32(Ac[(m + 8) * S_ASTRIDE + k + 4]);
            }
            uint32_t bf[8][2];
            #pragma unroll
            for (int nt = 0; nt < 8; ++nt) {
                int o = wn * 64 + nt * 8 + (lane >> 2);
                bf[nt][0] = __float_as_uint(Bc[k * G_BSTRIDE + o]);
                bf[nt][1] = __float_as_uint(Bc[(k + 4) * G_BSTRIDE + o]);
            }
            #pragma unroll
            for (int mt = 0; mt < 4; ++mt)
                #pragma unroll
                for (int nt = 0; nt < 8; ++nt)
                    mma_tf32(acc[mt][nt], af[mt], bf[nt]);
        }
    }

    float* part = g_part + (size_t)blockIdx.y * NN * DD;
    #pragma unroll
    for (int mt = 0; mt < 4; ++mt) {
        int n = n0 + wm * 64 + mt * 16 + (lane >> 2);
        #pragma unroll
        for (int nt = 0; nt < 8; ++nt) {
            int o = wn * 64 + nt * 8 + ((lane & 3) << 1);
            float2 r0, r1;
            r0.x = acc[mt][nt][0]; r0.y = acc[mt][nt][1];
            r1.x = acc[mt][nt][2]; r1.y = acc[mt][nt][3];
            *(float2*)&part[(size_t)n * DD + o]       = r0;
            *(float2*)&part[(size_t)(n + 8) * DD + o] = r1;
        }
    }
}

// ============================================================
// Kernel 4: deterministic split-K reduce (float4)
// ============================================================
__global__ __launch_bounds__(256) void reduce_kernel(float* __restrict__ out)
{
    size_t i = ((size_t)blockIdx.x * 256 + threadIdx.x) * 4;
    float4 s = *(const float4*)&g_part[i];
    #pragma unroll
    for (int p = 1; p < KSPLIT; ++p) {
        float4 v = *(const float4*)&g_part[(size_t)p * NN * DD + i];
        s.x += v.x; s.y += v.y; s.z += v.z; s.w += v.w;
    }
    *(float4*)&out[i] = s;
}

// ============================================================
extern "C" void kernel_launch(void* const* d_in, const int* in_sizes, int n_in,
                              void* d_out, int out_size)
{
    const float* x   = (const float*)d_in[0];
    const float* src = (const float*)d_in[1];
    const float* tgt = (const float*)d_in[2];
    const float* fw  = (const float*)d_in[3];
    const float* fb  = (const float*)d_in[4];
    float* out = (float*)d_out;

    const int g_smem = 4 * G_STG * sizeof(float);   // 204800
    const int s_smem = 4 * S_STG * sizeof(float);   // 217088
    cudaFuncSetAttribute(gather_kernel,  cudaFuncAttributeMaxDynamicSharedMemorySize, g_smem);
    cudaFuncSetAttribute(scatter_kernel, cudaFuncAttributeMaxDynamicSharedMemorySize, s_smem);

    node_transform_kernel<<<NN / 32, 256>>>(x, fw);
    gather_kernel<<<EE / 256, 256, g_smem>>>(src, tgt, fb);
    scatter_kernel<<<dim3(NN / 256, KSPLIT), 256, s_smem>>>(tgt);
    reduce_kernel<<<(NN * DD) / 1024, 256>>>(out);
}